// round 11
// baseline (speedup 1.0000x reference)
#include <cuda_runtime.h>

// LatticeQuantizer: hierarchical nested E8 lattice quantize (M=3, Q=4).
// Round 11: pack elementwise fp32 arithmetic into f32x2 (Blackwell dual-lane
// FFMA2/FADD2, rt=1 vs 2). Per-lane IEEE results are bit-identical; only
// provably order-free sums (exact integers / exact dyadic) are re-associated.
// All decision logic (argmax, ties, encode sequential distances, z/b/g
// chains) is R10-verbatim.

#define TINY_F    1.1920928955078125e-07f   // np.finfo(float32).eps = 2^-23
#define TINY_BITS 0x34000000

typedef unsigned long long u64;

static __device__ __forceinline__ u64 PK(float lo, float hi) {
    u64 r; asm("mov.b64 %0, {%1, %2};" : "=l"(r) : "f"(lo), "f"(hi)); return r;
}
static __device__ __forceinline__ void UPK(u64 v, float& lo, float& hi) {
    asm("mov.b64 {%0, %1}, %2;" : "=f"(lo), "=f"(hi) : "l"(v));
}
static __device__ __forceinline__ u64 ADD2(u64 a, u64 b) {
    u64 r; asm("add.rn.f32x2 %0, %1, %2;" : "=l"(r) : "l"(a), "l"(b)); return r;
}
static __device__ __forceinline__ u64 FMA2(u64 a, u64 b, u64 c) {
    u64 r; asm("fma.rn.f32x2 %0, %1, %2, %3;" : "=l"(r) : "l"(a), "l"(b), "l"(c)); return r;
}
static __device__ __forceinline__ u64 MUL2(u64 a, u64 b) {
    u64 r; asm("mul.rn.f32x2 %0, %1, %2;" : "=l"(r) : "l"(a), "l"(b)); return r;
}

// scalar faithful round (used in the b block)
static __device__ __forceinline__ float cround(float x) {
    float s = copysignf(TINY_F, x);
    return floorf((x - s) + 0.5f);
}

// -copysign(tiny, x) == copysign(tiny, -x): one LOP3
static __device__ __forceinline__ float negcs_tiny(float x) {
    return __int_as_float(((~__float_as_int(x)) & 0x80000000) | TINY_BITS);
}

// packed custom_round integer part: per lane floor(fl(fl(x - s) + 0.5))
static __device__ __forceinline__ u64 cround2(u64 x2, u64 H2) {
    float xl, xh; UPK(x2, xl, xh);
    u64 ns2 = PK(negcs_tiny(xl), negcs_tiny(xh));
    u64 v2  = ADD2(ADD2(x2, ns2), H2);      // fl(fl(x - s) + 0.5) per lane
    float vl, vh; UPK(v2, vl, vh);
    return PK(floorf(vl), floorf(vh));
}

struct Cand {
    u64   r2[4];     // packed residuals (exact)
    float r[8];      // scalar view
    float f[8];      // rounded coords (A: ints; B: pre +0.5) — valid if NEED_F
    float rk, rc, step;
    int   k, ke;     // ke = odd ? k : 8
    bool  odd;
};

template<bool NEED_F>
static __device__ __forceinline__ void prep(const u64 in2[4], u64 H2, u64 M1_2, Cand& c)
{
    u64 f2[4];
#pragma unroll
    for (int p = 0; p < 4; p++) {
        f2[p]   = cround2(in2[p], H2);
        c.r2[p] = FMA2(f2[p], M1_2, in2[p]);   // fl(in - f): f*(-1) exact
        UPK(c.r2[p], c.r[2*p], c.r[2*p+1]);
        if (NEED_F) UPK(f2[p], c.f[2*p], c.f[2*p+1]);
    }
    // sum of f: exact small integers -> any association bit-identical
    u64 s2 = ADD2(ADD2(f2[0], f2[1]), ADD2(f2[2], f2[3]));
    float slo, shi; UPK(s2, slo, shi);
    float sum = slo + shi;
    c.odd = (((int)sum) & 1) != 0;

    // argmax |r| — strict >, FIRST max wins (R9/R10-verbatim)
    float rk = c.r[0]; int k = 0;
#pragma unroll
    for (int i = 1; i < 8; i++) {
        bool gt = fabsf(c.r[i]) > fabsf(rk);
        rk = gt ? c.r[i] : rk;
        k  = gt ? i      : k;
    }
    // tie fallback: rk==0 => all r==0 => k==0 => xk == in[0]
    float in0lo, in0hi; UPK(in2[0], in0lo, in0hi);
    float tie = (in0lo >= 0.f) ? -1.f : 1.f;
    c.step = (rk > 0.f) ? 1.f : ((rk < 0.f) ? -1.f : tie);
    c.rk = rk; c.k = k;
    c.ke = c.odd ? k : 8;
    c.rc = rk - c.step;        // fl == fl(x_k - (f_k + step)), r exact
}

// ---- encode-path closest point (decision numerics R10-verbatim) ----
static __device__ __forceinline__ void cp_e8_enc(
    const u64 t2[4], float out[8], u64 H2, u64 MH2, u64 M1_2)
{
    Cand A; prep<true>(t2, H2, M1_2, A);

    u64 xs2[4];
#pragma unroll
    for (int p = 0; p < 4; p++) xs2[p] = ADD2(t2[p], MH2);   // fl(t - 0.5)
    Cand B; prep<true>(xs2, H2, M1_2, B);

    float t[8];
#pragma unroll
    for (int p = 0; p < 4; p++) UPK(t2[p], t[2*p], t[2*p+1]);

    // B materialized from fB in reference order (xs may have rounded);
    // A in residual form (exact). Sequential mul-then-sum distances.
    float d0 = 0.f, d1 = 0.f;
    float yB[8];
#pragma unroll
    for (int i = 0; i < 8; i++) {
        float addB = (i == B.ke) ? B.step : 0.f;
        yB[i] = (B.f[i] + addB) + 0.5f;
        float a  = (i == A.ke) ? A.rc : A.r[i];
        float rb = t[i] - yB[i];
        d0 = __fadd_rn(d0, __fmul_rn(a, a));
        d1 = __fadd_rn(d1, __fmul_rn(rb, rb));
    }
    bool p0 = d0 < d1;
#pragma unroll
    for (int i = 0; i < 8; i++) {
        float oA = (i == A.ke) ? (A.f[i] + A.step) : A.f[i];   // exact
        out[i] = p0 ? oA : yB[i];
    }
}

// ---- decode-path residuals: v = gq - cp_e8(gq), exact eighths domain ----
static __device__ __forceinline__ void cp_e8_dec_res(
    const u64 x2[4], float v[8], u64 H2, u64 MH2, u64 M1_2)
{
    Cand A; prep<false>(x2, H2, M1_2, A);

    u64 xs2[4];
#pragma unroll
    for (int p = 0; p < 4; p++) xs2[p] = ADD2(x2[p], MH2);    // exact here
    Cand B; prep<false>(xs2, H2, M1_2, B);

    // exact-domain distances: packed FMA accumulation + tie adjustment
    // (values are multiples of 1/64 with small sums -> order-free, proven)
    u64 dA2 = 0ull, dB2 = 0ull;
#pragma unroll
    for (int p = 0; p < 4; p++) {
        dA2 = FMA2(A.r2[p], A.r2[p], dA2);
        dB2 = FMA2(B.r2[p], B.r2[p], dB2);
    }
    float al, ah, bl, bh;
    UPK(dA2, al, ah); UPK(dB2, bl, bh);
    float d0 = al + ah;
    float d1 = bl + bh;
    float adjA = __fmul_rn(A.rc, A.rc) - __fmul_rn(A.rk, A.rk);  // exact
    float adjB = __fmul_rn(B.rc, B.rc) - __fmul_rn(B.rk, B.rk);
    d0 += A.odd ? adjA : 0.f;
    d1 += B.odd ? adjB : 0.f;
    bool p0 = d0 < d1;

    int   ksel = p0 ? A.ke : B.ke;
    float rcs  = p0 ? A.rc : B.rc;
#pragma unroll
    for (int i = 0; i < 8; i++) {
        float rs = p0 ? A.r[i] : B.r[i];
        v[i] = (i == ksel) ? rcs : rs;
    }
}

__global__ void __launch_bounds__(256)
lq_kernel(const float4* __restrict__ xin,
          const float* __restrict__ betap,
          const float* __restrict__ epsp,
          float4* __restrict__ outp,
          int nrows)
{
    int row = blockIdx.x * blockDim.x + threadIdx.x;
    if (row >= nrows) return;

    const u64 H2   = PK(0.5f, 0.5f);
    const u64 MH2  = PK(-0.5f, -0.5f);
    const u64 M1_2 = PK(-1.f, -1.f);
    const u64 Q2   = PK(0.25f, 0.25f);

    float beta = __ldg(betap);
    u64 eps2[4];
#pragma unroll
    for (int p = 0; p < 4; p++)
        eps2[p] = PK(__ldg(epsp + 2*p), __ldg(epsp + 2*p + 1));

    float4 a0 = __ldg(xin + 2 * row);
    float4 a1 = __ldg(xin + 2 * row + 1);

    bool beta1 = (beta == 1.0f);
    u64 xl2[4];
    if (beta1) {
        xl2[0] = PK(a0.x, a0.y); xl2[1] = PK(a0.z, a0.w);
        xl2[2] = PK(a1.x, a1.y); xl2[3] = PK(a1.z, a1.w);
    } else {
        xl2[0] = PK(__fdiv_rn(a0.x, beta), __fdiv_rn(a0.y, beta));
        xl2[1] = PK(__fdiv_rn(a0.z, beta), __fdiv_rn(a0.w, beta));
        xl2[2] = PK(__fdiv_rn(a1.x, beta), __fdiv_rn(a1.y, beta));
        xl2[3] = PK(__fdiv_rn(a1.z, beta), __fdiv_rn(a1.w, beta));
    }

    // layer-0 encode input: t = xl + eps (packed, per-lane identical)
    u64 t2[4];
#pragma unroll
    for (int p = 0; p < 4; p++) t2[p] = ADD2(xl2[p], eps2[p]);

    float xh[8] = {0.f, 0.f, 0.f, 0.f, 0.f, 0.f, 0.f, 0.f};

#pragma unroll
    for (int m = 0; m < 3; m++) {
        // ---- encode layer m ----
        float cp[8];
        cp_e8_enc(t2, cp, H2, MH2, M1_2);

        // z = cp @ G_inv (analytic forward solve; exact quarter-integers)
        float z[8];
        z[0] = 0.5f * cp[0];
        float sum06 = z[0];
#pragma unroll
        for (int i = 1; i < 7; i++) { z[i] = cp[i] + z[i - 1]; sum06 += z[i]; }
        z[7] = 2.f * cp[7] - sum06;

        // b = custom_round(fmod(z,4)); fmod exact; cround REQUIRED
        float b[8];
#pragma unroll
        for (int i = 0; i < 8; i++) {
            float q = truncf(z[i] * 0.25f);
            float r = __fmaf_rn(-4.f, q, z[i]);   // exact (dyadic)
            b[i] = cround(r);
        }

        // next layer input: t = fma(cp, 1/Q, eps) == fl(fl(cp*0.25)+eps)
        if (m < 2) {
#pragma unroll
            for (int p = 0; p < 4; p++) {
                u64 cp2 = PK(cp[2*p], cp[2*p+1]);
                t2[p] = FMA2(cp2, Q2, eps2[p]);
            }
        }

        // ---- decode layer m: xi = g - 4*cp_e8(g/4) == 4*v ----
        float h = 0.5f * b[7];
        float g[8];
        g[0] = 2.f * b[0] - b[1] + h;
#pragma unroll
        for (int j = 1; j < 6; j++) g[j] = b[j] - b[j + 1] + h;
        g[6] = b[6] + h;
        g[7] = h;

        u64 gq2[4];
#pragma unroll
        for (int p = 0; p < 4; p++)
            gq2[p] = MUL2(PK(g[2*p], g[2*p+1]), Q2);   // exact eighths

        float v[8];
        cp_e8_dec_res(gq2, v, H2, MH2, M1_2);

        float c4 = (m == 0) ? 4.f : ((m == 1) ? 16.f : 64.f);
#pragma unroll
        for (int i = 0; i < 8; i++)
            xh[i] = __fmaf_rn(c4, v[i], xh[i]);        // exact dyadic
    }

    float4 o0, o1;
    if (beta1) {
        o0.x = xh[0]; o0.y = xh[1]; o0.z = xh[2]; o0.w = xh[3];
        o1.x = xh[4]; o1.y = xh[5]; o1.z = xh[6]; o1.w = xh[7];
    } else {
        o0.x = beta * xh[0]; o0.y = beta * xh[1];
        o0.z = beta * xh[2]; o0.w = beta * xh[3];
        o1.x = beta * xh[4]; o1.y = beta * xh[5];
        o1.z = beta * xh[6]; o1.w = beta * xh[7];
    }
    outp[2 * row]     = o0;
    outp[2 * row + 1] = o1;
}

extern "C" void kernel_launch(void* const* d_in, const int* in_sizes, int n_in,
                              void* d_out, int out_size)
{
    const float* x = (const float*)d_in[0];
    const float* beta = nullptr;
    const float* eps  = nullptr;
    for (int i = 1; i < n_in; i++) {
        if (in_sizes[i] == 1) beta = (const float*)d_in[i];
        else if (in_sizes[i] == 8) eps = (const float*)d_in[i];
    }
    int nrows = in_sizes[0] / 8;
    int threads = 256;
    int blocks = (nrows + threads - 1) / threads;
    lq_kernel<<<blocks, threads>>>((const float4*)x, beta, eps, (float4*)d_out, nrows);
}